// round 4
// baseline (speedup 1.0000x reference)
#include <cuda_runtime.h>
#include <cuda_bf16.h>
#include <cstdint>

// Loss_58042188038797:
//   ri = i / (n*(n+1)/2)
//   p_win = victor==0 ? f[:,0] : f[:,1]
//   loss = -sum( (log(p_win) - (f[:,0]-0.5)^2) * ri )
//
// Single fused kernel. HBM-bound read-once stream (12 B/elem):
//  - __ldcs streaming loads (evict-first; data never reused)
//  - 2-way unrolled grid-stride loop (6 x 128-bit LDGs batched -> MLP)
//  - warp+block reduce, per-block atomicAdd to a device global,
//    last-block-done pattern writes -total to d_out and resets the
//    globals (deterministic across graph replays, no zeroing kernel).

static constexpr int BLOCK = 256;
static constexpr int GRID  = 148 * 8;

__device__ float        g_partial = 0.0f;
__device__ unsigned int g_count   = 0u;

__device__ __forceinline__ float elem_term(float f0, float f1, int v) {
    float p = (v == 0) ? f0 : f1;
    float d = f0 - 0.5f;
    return __logf(p) - d * d;
}

__device__ __forceinline__ float group4(const float4* __restrict__ fo,
                                        const int4* __restrict__ pv,
                                        int i, float inv_denom) {
    float4 a = __ldcs(&fo[2 * i]);
    float4 b = __ldcs(&fo[2 * i + 1]);
    int4   v = __ldcs(&pv[i]);
    float base = (float)(4 * i);   // 4i < 2^24 -> exact in f32
    float s = 0.0f;
    s = fmaf(elem_term(a.x, a.y, v.x), (base + 0.0f) * inv_denom, s);
    s = fmaf(elem_term(a.z, a.w, v.y), (base + 1.0f) * inv_denom, s);
    s = fmaf(elem_term(b.x, b.y, v.z), (base + 2.0f) * inv_denom, s);
    s = fmaf(elem_term(b.z, b.w, v.w), (base + 3.0f) * inv_denom, s);
    return s;
}

__global__ __launch_bounds__(BLOCK) void loss_kernel(
    const float4* __restrict__ fo,   // final_out as float4 (2 elems/vec)
    const int4*  __restrict__ pv,    // point_victor as int4 (4 elems/vec)
    float* __restrict__ out,
    int n4,                          // n / 4
    float inv_denom)                 // 2 / (n*(n+1))
{
    float acc = 0.0f;
    const int stride = gridDim.x * blockDim.x;
    int i = blockIdx.x * blockDim.x + threadIdx.x;

    // 2-way unrolled grid-stride: batch 6 x 128-bit loads per iteration
    for (; i + stride < n4; i += 2 * stride) {
        acc += group4(fo, pv, i, inv_denom);
        acc += group4(fo, pv, i + stride, inv_denom);
    }
    if (i < n4)
        acc += group4(fo, pv, i, inv_denom);

    // warp reduce
    #pragma unroll
    for (int o = 16; o > 0; o >>= 1)
        acc += __shfl_down_sync(0xFFFFFFFFu, acc, o);

    __shared__ float smem[BLOCK / 32];
    const int lane = threadIdx.x & 31;
    const int wid  = threadIdx.x >> 5;
    if (lane == 0) smem[wid] = acc;
    __syncthreads();

    if (wid == 0) {
        acc = (lane < BLOCK / 32) ? smem[lane] : 0.0f;
        #pragma unroll
        for (int o = 4; o > 0; o >>= 1)
            acc += __shfl_down_sync(0xFFFFFFFFu, acc, o);

        if (lane == 0) {
            atomicAdd(&g_partial, acc);
            __threadfence();
            unsigned int done = atomicAdd(&g_count, 1u);
            if (done == gridDim.x - 1) {
                // last block: read+reset total, reset counter, emit loss
                float total = atomicExch(&g_partial, 0.0f);
                atomicExch(&g_count, 0u);
                out[0] = -total;
            }
        }
    }
}

extern "C" void kernel_launch(void* const* d_in, const int* in_sizes, int n_in,
                              void* d_out, int out_size) {
    const float4* fo = (const float4*)d_in[0];   // final_out (N,2) f32
    const int4*   pv = (const int4*)d_in[1];     // point_victor (N) i32
    float* out = (float*)d_out;

    const int n  = in_sizes[1];                  // N
    const int n4 = n / 4;                        // N = 2^24, divisible by 4

    const double nd = (double)n;
    const float inv_denom = (float)(2.0 / (nd * (nd + 1.0)));

    loss_kernel<<<GRID, BLOCK>>>(fo, pv, out, n4, inv_denom);
}

// round 5
// speedup vs baseline: 1.0236x; 1.0236x over previous
#include <cuda_runtime.h>
#include <cuda_bf16.h>
#include <cstdint>

// Loss_58042188038797:
//   ri = i / (n*(n+1)/2)
//   p_win = victor==0 ? f[:,0] : f[:,1]
//   loss = -sum( (log(p_win) - (f[:,0]-0.5)^2) * ri )
//
// Single fused kernel = R3's loop body (plain cached float4/int4 loads,
// simple grid-stride — measured 80.9% DRAM) + last-block-done finish
// (removes the separate zeroing launch's ~2.8us).

static constexpr int BLOCK = 256;
static constexpr int GRID  = 148 * 8;

__device__ float        g_partial = 0.0f;
__device__ unsigned int g_count   = 0u;

__global__ __launch_bounds__(BLOCK) void loss_kernel(
    const float4* __restrict__ fo,   // final_out as float4 (2 elems/vec)
    const int4*  __restrict__ pv,    // point_victor as int4 (4 elems/vec)
    float* __restrict__ out,
    int n4,                          // n / 4
    float inv_denom)                 // 2 / (n*(n+1))
{
    float acc = 0.0f;
    const int stride = gridDim.x * blockDim.x;

    for (int i = blockIdx.x * blockDim.x + threadIdx.x; i < n4; i += stride) {
        float4 a = fo[2 * i];        // elems 4i, 4i+1
        float4 b = fo[2 * i + 1];    // elems 4i+2, 4i+3
        int4   v = pv[i];
        float base = (float)(4 * i); // 4i < 2^24 -> exact in f32

        {
            float p = (v.x == 0) ? a.x : a.y;
            float d = a.x - 0.5f;
            float t = __logf(p) - d * d;
            acc = fmaf(t, (base + 0.0f) * inv_denom, acc);
        }
        {
            float p = (v.y == 0) ? a.z : a.w;
            float d = a.z - 0.5f;
            float t = __logf(p) - d * d;
            acc = fmaf(t, (base + 1.0f) * inv_denom, acc);
        }
        {
            float p = (v.z == 0) ? b.x : b.y;
            float d = b.x - 0.5f;
            float t = __logf(p) - d * d;
            acc = fmaf(t, (base + 2.0f) * inv_denom, acc);
        }
        {
            float p = (v.w == 0) ? b.z : b.w;
            float d = b.z - 0.5f;
            float t = __logf(p) - d * d;
            acc = fmaf(t, (base + 3.0f) * inv_denom, acc);
        }
    }

    // warp reduce
    #pragma unroll
    for (int o = 16; o > 0; o >>= 1)
        acc += __shfl_down_sync(0xFFFFFFFFu, acc, o);

    __shared__ float smem[BLOCK / 32];
    const int lane = threadIdx.x & 31;
    const int wid  = threadIdx.x >> 5;
    if (lane == 0) smem[wid] = acc;
    __syncthreads();

    if (wid == 0) {
        acc = (lane < BLOCK / 32) ? smem[lane] : 0.0f;
        #pragma unroll
        for (int o = 4; o > 0; o >>= 1)
            acc += __shfl_down_sync(0xFFFFFFFFu, acc, o);

        if (lane == 0) {
            atomicAdd(&g_partial, acc);
            __threadfence();
            unsigned int done = atomicAdd(&g_count, 1u);
            if (done == gridDim.x - 1) {
                // last block: read+reset total, reset counter, emit loss
                float total = atomicExch(&g_partial, 0.0f);
                atomicExch(&g_count, 0u);
                out[0] = -total;
            }
        }
    }
}

extern "C" void kernel_launch(void* const* d_in, const int* in_sizes, int n_in,
                              void* d_out, int out_size) {
    const float4* fo = (const float4*)d_in[0];   // final_out (N,2) f32
    const int4*   pv = (const int4*)d_in[1];     // point_victor (N) i32
    float* out = (float*)d_out;

    const int n  = in_sizes[1];                  // N
    const int n4 = n / 4;                        // N = 2^24, divisible by 4

    const double nd = (double)n;
    const float inv_denom = (float)(2.0 / (nd * (nd + 1.0)));

    loss_kernel<<<GRID, BLOCK>>>(fo, pv, out, n4, inv_denom);
}